// round 8
// baseline (speedup 1.0000x reference)
#include <cuda_runtime.h>
#include <math.h>

#define BN 4096
#define KN 3000
#define KPADC 3072        // padded columns
#define CN 8
#define NBLK 148
#define NTHR 256
#define RPB 28            // ceil(4096/148)
#define CAP 1024          // max nz per row (power of 2)
#define BCAP (RPB*CAP)    // max nz per block
#define COLSP 21          // ceil(3000/148)
#define LGRP 512
#define TOLF 1e-3f
#define THRESH -36.0f
#define FXSCALE 4398046511104.0f       // 2^42
#define FXINV   (1.0f/4398046511104.0f)

typedef unsigned long long ull;

// ---------------- static scratch ----------------
static __device__ unsigned short g_nzi[2][BN][CAP];   // column index per nz
static __device__ float g_nzv[2][BN][CAP];            // exp value per nz
static __device__ float g_nzw[2][BN][CAP];            // final P value per nz
static __device__ int   g_cnt[2][BN];
static __device__ unsigned g_bk[2][NBLK][BCAP];       // packed k | (localrow<<16)
static __device__ float g_bv[2][NBLK][BCAP];
static __device__ int   g_bcnt[2][NBLK];
static __device__ float g_cpart[2][NBLK][KPADC];      // fp32 column partials
static __device__ float g_c[2][KPADC];                // reduced column sums
static __device__ float g_v2[2][KPADC];               // final v
static __device__ float g_r[2][BN];                   // row sums (initial)
static __device__ volatile unsigned g_arrive[NBLK];
static __device__ volatile unsigned g_flagw[4];       // [parity][side]
static __device__ float g_rowent[2][BN];
static __device__ float g_rowmaxq[2][BN];
static __device__ float g_losspart[(size_t)CN * LGRP * 3];

struct Args {
    const float* lg[8];
    const int* ia;
    const int* ib;
};

__device__ __forceinline__ float warp_max(float v) {
#pragma unroll
    for (int o = 16; o; o >>= 1) v = fmaxf(v, __shfl_xor_sync(0xffffffffu, v, o));
    return v;
}
__device__ __forceinline__ float warp_sum(float v) {
#pragma unroll
    for (int o = 16; o; o >>= 1) v += __shfl_xor_sync(0xffffffffu, v, o);
    return v;
}

// ---------------- kernel 1: sparse build (single HBM pass) ----------------
__global__ void __launch_bounds__(256) buildq_kernel(Args a) {
    __shared__ float s_x[KN];
    __shared__ float smx[8];
    __shared__ int s_wc[8], s_woff[8], s_base;

    const int s = blockIdx.y;
    const int row = blockIdx.x;
    const int idx = (s == 0) ? *a.ia : *a.ib;
    const float* __restrict__ xr = a.lg[idx] + (size_t)row * KN;
    const int tid = threadIdx.x, wid = tid >> 5, lane = tid & 31;

    // infra zeroing (once per launch)
    if (blockIdx.x == 0 && s == 0) {
        if (tid < NBLK) g_arrive[tid] = 0u;
        if (tid < 4) g_flagw[tid] = 0u;
    }

    // single global pass: stage + row max
    float m = -3.402823466e38f;
    for (int k = tid; k < KN; k += 256) {
        float x = xr[k];
        s_x[k] = x;
        m = fmaxf(m, x);
    }
    m = warp_max(m);
    if (lane == 0) smx[wid] = m;
    __syncthreads();
    if (wid == 0) {
        float t = (lane < 8) ? smx[lane] : -3.402823466e38f;
        t = warp_max(t);
        if (lane == 0) smx[0] = t;
    }
    if (tid == 0) s_base = 0;
    __syncthreads();
    m = smx[0];

    // deterministic k-ordered compaction from smem
    float rsum = 0.f;
    for (int k0 = 0; k0 < KN; k0 += 256) {
        const int col = k0 + tid;
        bool pred = false;
        float val = 0.f;
        if (col < KN) {
            float d = 20.0f * (s_x[col] - m);
            if (d > THRESH) { pred = true; val = __expf(d); }
        }
        unsigned mask = __ballot_sync(0xffffffffu, pred);
        int wcnt = __popc(mask);
        if (lane == 0) s_wc[wid] = wcnt;
        __syncthreads();
        if (tid == 0) {
            int b = s_base;
#pragma unroll
            for (int w = 0; w < 8; w++) { s_woff[w] = b; b += s_wc[w]; }
            s_base = b;
        }
        __syncthreads();
        if (pred) {
            int pos = s_woff[wid] + __popc(mask & ((1u << lane) - 1u));
            if (pos < CAP) {
                g_nzi[s][row][pos] = (unsigned short)col;
                g_nzv[s][row][pos] = val;
                rsum += val;
            }
        }
        __syncthreads();
    }
    if (tid == 0) g_cnt[s][row] = min(s_base, CAP);

    rsum = warp_sum(rsum);
    if (lane == 0) smx[wid] = rsum;
    __syncthreads();
    if (wid == 0) {
        float t = (lane < 8) ? smx[lane] : 0.f;
        t = warp_sum(t);
        if (lane == 0) g_r[s][row] = t;
    }
}

// ---------------- kernel 1b: block-flattened lists ----------------
__global__ void __launch_bounds__(256) blockify_kernel() {
    const int s = blockIdx.y, bi = blockIdx.x;
    const int tid = threadIdx.x;
    const int row0 = bi * RPB;
    const int nrow = max(0, min(BN, row0 + RPB) - row0);
    __shared__ int s_off[RPB + 1];
    if (tid == 0) {
        int o = 0;
        for (int b = 0; b < nrow; b++) { s_off[b] = o; o += g_cnt[s][row0 + b]; }
        s_off[nrow] = o;
        g_bcnt[s][bi] = o;
    }
    __syncthreads();
    for (int j = tid; j < nrow * CAP; j += 256) {
        int b = j >> 10, i = j & (CAP - 1);
        if (i < g_cnt[s][row0 + b]) {
            int dst = s_off[b] + i;
            g_bk[s][bi][dst] = (unsigned)g_nzi[s][row0 + b][i] | ((unsigned)b << 16);
            g_bv[s][bi][dst] = g_nzv[s][row0 + b][i];
        }
    }
}

// ---------------- kernel 2: persistent sparse double-Sinkhorn ----------------
#define DSMEM_SZ (49152 + 24576 + 1344 + 1024)

__global__ void __launch_bounds__(NTHR, 1) sinkhorn_kernel() {
    extern __shared__ ull dsm[];
    ull* s_c = dsm;                                        // [2][3072] fixed-point scatter
    float* s_v = (float*)(dsm + 2 * KPADC);                // [2][3072]
    float* s_tmp = (float*)(s_v + 2 * KPADC);              // [8*COLSP] cross-warp reduce
    float* s_r = s_tmp + 8 * COLSP + 8;                    // [2][28]
    float* s_u = s_r + 2 * RPB;                            // [2][28]
    float* s_red = s_u + 2 * RPB;                          // [16]
    int* s_cnt = (int*)(s_red + 16);                       // [2][28]

    const int tid = threadIdx.x, bi = blockIdx.x;
    const int wid = tid >> 5, lane = tid & 31;
    const float TGT = (float)(4096.0 / 3000.0);
    const int row0 = bi * RPB;
    const int nrow = max(0, min(BN, row0 + RPB) - row0);
    const int k0 = bi * COLSP;
    unsigned gen = 0;

    for (int j = tid; j < 2 * KPADC; j += NTHR) s_c[j] = 0ull;
    for (int s = 0; s < 2; s++)
        if (tid < nrow) {
            s_r[s * RPB + tid] = g_r[s][row0 + tid];
            s_cnt[s * RPB + tid] = g_cnt[s][row0 + tid];
        }
    __syncthreads();

    bool done0 = false, done1 = false;
    int it = 0;

#define GRIDBAR() do { \
        __syncthreads(); \
        __threadfence(); \
        gen++; \
        if (tid == 0) g_arrive[bi] = gen; \
        if (tid < NBLK) { while (g_arrive[tid] < gen) { __nanosleep(20); } } \
        __syncthreads(); \
        __threadfence(); \
    } while (0)

    while (!(done0 && done1)) {
        const int p = it & 1;
        // --- phase A: u = 1/(r+TINY); fixed-point smem scatter; export fp32 partials ---
        for (int s = 0; s < 2; s++) {
            if (s == 0 ? done0 : done1) continue;
            if (tid < nrow)
                s_u[s * RPB + tid] = 1.0f / (s_r[s * RPB + tid] + 1e-12f);
        }
        __syncthreads();
        for (int s = 0; s < 2; s++) {
            if (s == 0 ? done0 : done1) continue;
            const int bc = g_bcnt[s][bi];
            for (int j = tid; j < bc; j += NTHR) {
                unsigned pk = g_bk[s][bi][j];
                float val = g_bv[s][bi][j];
                float t = s_u[s * RPB + (pk >> 16)] * val;
                atomicAdd(&s_c[s * KPADC + (pk & 0xFFFFu)], __float2ull_rn(t * FXSCALE));
            }
        }
        __syncthreads();
        for (int s = 0; s < 2; s++) {
            if (s == 0 ? done0 : done1) continue;
            for (int j = tid; j < KPADC; j += NTHR) {
                g_cpart[s][bi][j] = (float)s_c[s * KPADC + j] * FXINV;
                s_c[s * KPADC + j] = 0ull;
            }
        }
        GRIDBAR();
        // --- phase B: coalesced owner-column reduce -> c ---
        if (bi == 0 && tid < 2) g_flagw[(p ^ 1) * 2 + tid] = 0u;
        for (int s = 0; s < 2; s++) {
            if (s == 0 ? done0 : done1) continue;
            float facc = 0.f;
            if (lane < COLSP && k0 + lane < KN)
                for (int i = wid; i < NBLK; i += 8) facc += g_cpart[s][i][k0 + lane];
            if (lane < COLSP) s_tmp[wid * COLSP + lane] = facc;
            __syncthreads();
            if (wid == 0 && lane < COLSP && k0 + lane < KN) {
                float t = 0.f;
#pragma unroll
                for (int w = 0; w < 8; w++) t += s_tmp[w * COLSP + lane];
                g_c[s][k0 + lane] = t;
            }
            __syncthreads();
        }
        GRIDBAR();
        // --- phase C: stage v, col err, gather r, row err ---
        {
            float ce0 = 0.f, ce1 = 0.f;
            for (int j = tid; j < 2 * KPADC; j += NTHR) {
                const int s = j / KPADC, k = j % KPADC;
                float v = 0.f;
                if (k < KN && !(s == 0 ? done0 : done1)) {
                    float c = g_c[s][k];
                    v = TGT / (c + 1e-12f);
                    float e = fabsf(v * c - TGT);
                    if (s == 0) ce0 = fmaxf(ce0, e); else ce1 = fmaxf(ce1, e);
                }
                s_v[j] = v;
            }
            ce0 = warp_max(ce0);
            ce1 = warp_max(ce1);
            if (lane == 0) { s_red[wid] = ce0; s_red[8 + wid] = ce1; }
            __syncthreads();
            if (tid == 0) {
                float t0 = 0.f, t1 = 0.f;
                for (int w = 0; w < 8; w++) { t0 = fmaxf(t0, s_red[w]); t1 = fmaxf(t1, s_red[8 + w]); }
                if (t0 > TOLF) g_flagw[p * 2 + 0] = 1u;
                if (t1 > TOLF) g_flagw[p * 2 + 1] = 1u;
            }
            __syncthreads();
        }
        for (int job = wid; job < 2 * RPB; job += 8) {
            const int s = job / RPB, b = job % RPB;
            if ((s == 0 ? done0 : done1) || b >= nrow) continue;
            const int cnt = s_cnt[s * RPB + b];
            float acc = 0.f;
            for (int i = lane; i < cnt; i += 32) {
                int k = g_nzi[s][row0 + b][i];
                acc = fmaf(g_nzv[s][row0 + b][i], s_v[s * KPADC + k], acc);
            }
            acc = warp_sum(acc);
            if (lane == 0) {
                s_r[s * RPB + b] = acc;
                if (fabsf(s_u[s * RPB + b] * acc - 1.0f) > TOLF) g_flagw[p * 2 + s] = 1u;
            }
        }
        GRIDBAR();
        it++;
        if (!done0) done0 = (it >= 3) && ((it >= 100) || (g_flagw[p * 2 + 0] == 0u));
        if (!done1) done1 = (it >= 3) && ((it >= 100) || (g_flagw[p * 2 + 1] == 0u));
    }

    // ---------------- finalize ----------------
    // F1: u1 = u/clip(u*r); scatter with u1
    for (int s = 0; s < 2; s++)
        if (tid < nrow) {
            float u = s_u[s * RPB + tid], r = s_r[s * RPB + tid];
            s_u[s * RPB + tid] = u / fmaxf(u * r, 1e-12f);
        }
    __syncthreads();
    for (int s = 0; s < 2; s++) {
        const int bc = g_bcnt[s][bi];
        for (int j = tid; j < bc; j += NTHR) {
            unsigned pk = g_bk[s][bi][j];
            float val = g_bv[s][bi][j];
            float t = s_u[s * RPB + (pk >> 16)] * val;
            atomicAdd(&s_c[s * KPADC + (pk & 0xFFFFu)], __float2ull_rn(t * FXSCALE));
        }
    }
    __syncthreads();
    for (int j = tid; j < 2 * KPADC; j += NTHR)
        g_cpart[j / KPADC][bi][j % KPADC] = (float)s_c[j] * FXINV;
    GRIDBAR();
    // F2: v2 = v*TGT/clip(v*c2), coalesced owner reduce
    for (int s = 0; s < 2; s++) {
        float facc = 0.f;
        if (lane < COLSP && k0 + lane < KN)
            for (int i = wid; i < NBLK; i += 8) facc += g_cpart[s][i][k0 + lane];
        if (lane < COLSP) s_tmp[wid * COLSP + lane] = facc;
        __syncthreads();
        if (wid == 0 && lane < COLSP && k0 + lane < KN) {
            float c2 = 0.f;
#pragma unroll
            for (int w = 0; w < 8; w++) c2 += s_tmp[w * COLSP + lane];
            float v = TGT / (g_c[s][k0 + lane] + 1e-12f);
            g_v2[s][k0 + lane] = v * TGT / fmaxf(v * c2, 1e-12f);
        }
        __syncthreads();
    }
    GRIDBAR();
    // F3: r2 = Q v2; u2; entropy + rowmax; store w
    for (int j = tid; j < 2 * KPADC; j += NTHR) {
        const int s = j / KPADC, k = j % KPADC;
        s_v[j] = (k < KN) ? g_v2[s][k] : 0.f;
    }
    __syncthreads();
    for (int job = wid; job < 2 * RPB; job += 8) {
        const int s = job / RPB, b = job % RPB;
        if (b >= nrow) continue;
        const int cnt = s_cnt[s * RPB + b];
        float acc = 0.f;
        for (int i = lane; i < cnt; i += 32) {
            int k = g_nzi[s][row0 + b][i];
            acc = fmaf(g_nzv[s][row0 + b][i], s_v[s * KPADC + k], acc);
        }
        acc = warp_sum(acc);
        float u1 = s_u[s * RPB + b];
        float u2 = u1 / fmaxf(u1 * acc, 1e-12f);
        float se = 0.f, mq = 0.f;
        for (int i = lane; i < cnt; i += 32) {
            int k = g_nzi[s][row0 + b][i];
            float w = u2 * g_nzv[s][row0 + b][i] * s_v[s * KPADC + k];
            g_nzw[s][row0 + b][i] = w;
            se = fmaf(w, __logf(w + 1e-12f), se);
            mq = fmaxf(mq, w);
        }
        se = warp_sum(se);
        mq = warp_max(mq);
        if (lane == 0) {
            g_rowent[s][row0 + b] = se;
            g_rowmaxq[s][row0 + b] = mq;
        }
    }
}

// ---------------- kernel 3: loss (single HBM pass, smem-staged rows) ----------------
__global__ void __launch_bounds__(256) loss_kernel(Args a) {
    __shared__ float s_x[KN];
    __shared__ float s_red[8];
    __shared__ float s_ab[2];
    const int tid = threadIdx.x, wid = tid >> 5, lane = tid & 31;
    const int c = blockIdx.y;
    const int ia = *a.ia, ib = *a.ib;
    const bool useA = (c != ia), useB = (c != ib);
    const float* __restrict__ lgp = a.lg[c];

    float acc_lse = 0.f, acc_da = 0.f, acc_db = 0.f;
    const int b0 = blockIdx.x * 8;
    for (int rr = 0; rr < 8; rr++) {
        const int b = b0 + rr;
        const float* __restrict__ xr = lgp + (size_t)b * KN;
        float m = -3.402823466e38f;
        for (int k = tid; k < KN; k += 256) {
            float x = xr[k];
            s_x[k] = x;
            m = fmaxf(m, x);
        }
        m = warp_max(m);
        if (lane == 0) s_red[wid] = m;
        __syncthreads();
        if (wid == 0) {
            float t = (lane < 8) ? s_red[lane] : -3.402823466e38f;
            t = warp_max(t);
            if (lane == 0) s_red[0] = t;
        }
        __syncthreads();
        m = s_red[0];
        __syncthreads();

        float se = 0.f;
        for (int k = tid; k < KN; k += 256) {
            float d = 10.0f * (s_x[k] - m);
            if (d > -18.f) se += __expf(d);
        }
        se = warp_sum(se);
        if (lane == 0) s_red[wid] = se;

        if (wid < 2) {
            const int s = wid;
            float dd = 0.f;
            if (s == 0 ? useA : useB) {
                const int cnt = g_cnt[s][b];
                for (int i = lane; i < cnt; i += 32)
                    dd = fmaf(g_nzw[s][b][i], s_x[(int)g_nzi[s][b][i]], dd);
            }
            dd = warp_sum(dd);
            if (lane == 0) s_ab[s] = dd;
        }
        __syncthreads();
        if (tid == 0) {
            float ts = 0.f;
            for (int w = 0; w < 8; w++) ts += s_red[w];
            acc_lse += 10.0f * m + logf(ts);
            acc_da += s_ab[0];
            acc_db += s_ab[1];
        }
        __syncthreads();
    }
    if (tid == 0) {
        float* p = &g_losspart[((size_t)c * LGRP + blockIdx.x) * 3];
        p[0] = acc_lse;
        p[1] = acc_da;
        p[2] = acc_db;
    }
}

// ---------------- kernel 4: final scalar reduction ----------------
__device__ double bredD(double v, double* sd) {
    const int tid = threadIdx.x, wid = tid >> 5, lane = tid & 31;
#pragma unroll
    for (int o = 16; o; o >>= 1) v += __shfl_xor_sync(0xffffffffu, v, o);
    if (lane == 0) sd[wid] = v;
    __syncthreads();
    double t = 0.0;
    if (wid == 0) {
        t = sd[lane];
#pragma unroll
        for (int o = 16; o; o >>= 1) t += __shfl_xor_sync(0xffffffffu, t, o);
    }
    __syncthreads();
    return t;
}

__global__ void __launch_bounds__(1024) fin_kernel(Args a, float* out) {
    __shared__ double sd[32];
    const int tid = threadIdx.x;
    const int ia = *a.ia, ib = *a.ib;
    double se0 = 0, se1 = 0, sm0 = 0, sm1 = 0, sl = 0;
    for (int b = tid; b < BN; b += 1024) {
        se0 += (double)g_rowent[0][b];
        se1 += (double)g_rowent[1][b];
        sm0 += (double)g_rowmaxq[0][b];
        sm1 += (double)g_rowmaxq[1][b];
    }
    for (int i = tid; i < CN * LGRP; i += 1024) {
        int c = i / LGRP;
        const float* p = &g_losspart[(size_t)i * 3];
        double lse = p[0], da = p[1], db = p[2];
        if (c != ia) sl += lse - 10.0 * da;
        if (c != ib) sl += lse - 10.0 * db;
    }
    se0 = bredD(se0, sd);
    se1 = bredD(se1, sd);
    sm0 = bredD(sm0, sd);
    sm1 = bredD(sm1, sd);
    sl = bredD(sl, sd);
    if (tid == 0) {
        out[0] = (float)(sl / (14.0 * BN));
        out[1] = (float)(0.5 * ((-se0 / BN) + (-se1 / BN)));
        out[2] = (float)(0.5 * ((sm0 + sm1) / BN));
    }
}

// ---------------- entry ----------------
extern "C" void kernel_launch(void* const* d_in, const int* in_sizes, int n_in,
                              void* d_out, int out_size) {
    Args a;
    for (int i = 0; i < 8; i++) a.lg[i] = (const float*)d_in[i];
    a.ia = (const int*)d_in[8];
    a.ib = (const int*)d_in[9];

    cudaFuncSetAttribute(sinkhorn_kernel,
                         cudaFuncAttributeMaxDynamicSharedMemorySize, DSMEM_SZ);

    buildq_kernel<<<dim3(BN, 2), 256>>>(a);
    blockify_kernel<<<dim3(NBLK, 2), 256>>>();
    sinkhorn_kernel<<<NBLK, NTHR, DSMEM_SZ>>>();
    loss_kernel<<<dim3(LGRP, CN), 256>>>(a);
    fin_kernel<<<1, 1024>>>(a, (float*)d_out);
}

// round 12
// speedup vs baseline: 1.6141x; 1.6141x over previous
#include <cuda_runtime.h>
#include <math.h>

#define BN 4096
#define KN 3000
#define KPADC 3072        // padded columns
#define CN 8
#define NBLK 148
#define NTHR 512
#define RPB 28            // ceil(4096/148)
#define CAP 1024          // max nz per row (power of 2)
#define BCAP (RPB*CAP)    // max nz per block
#define COLSP 21          // ceil(3000/148)
#define TOLF 1e-3f
#define THRESH -36.0f
#define FXSCALE 4398046511104.0f       // 2^42
#define FXINV   (1.0f/4398046511104.0f)

typedef unsigned long long ull;

// ---------------- static scratch ----------------
static __device__ unsigned short g_nzi[2][BN][CAP];   // column index per nz
static __device__ float g_nzv[2][BN][CAP];            // exp value per nz
static __device__ float g_nzw[2][BN][CAP];            // final P value per nz
static __device__ int   g_cnt[2][BN];
static __device__ unsigned g_bk[2][NBLK][BCAP];       // packed k | (localrow<<16)
static __device__ float g_bv[2][NBLK][BCAP];
static __device__ int   g_bcnt[2][NBLK];
static __device__ float g_cpart[2][NBLK][KPADC];      // fp32 column partials
static __device__ float g_c[2][KPADC];                // reduced column sums
static __device__ float g_v2[2][KPADC];               // final v
static __device__ float g_r[2][BN];                   // row sums (initial)
static __device__ unsigned g_count;                   // central barrier counter
static __device__ volatile unsigned g_release;        // central barrier release word
static __device__ volatile unsigned g_flagw[4];       // [parity][side]
static __device__ float g_rowent[2][BN];
static __device__ float g_rowmaxq[2][BN];
static __device__ float g_losspart[(size_t)CN * BN * 3];

struct Args {
    const float* lg[8];
    const int* ia;
    const int* ib;
};

__device__ __forceinline__ float warp_max(float v) {
#pragma unroll
    for (int o = 16; o; o >>= 1) v = fmaxf(v, __shfl_xor_sync(0xffffffffu, v, o));
    return v;
}
__device__ __forceinline__ float warp_sum(float v) {
#pragma unroll
    for (int o = 16; o; o >>= 1) v += __shfl_xor_sync(0xffffffffu, v, o);
    return v;
}

// ---------------- kernel 1: sparse build (single HBM pass) — R7 arithmetic ----------------
__global__ void __launch_bounds__(256) buildq_kernel(Args a) {
    __shared__ float s_x[KN];
    __shared__ float smx[8];
    __shared__ int s_wc[8], s_woff[8], s_base;

    const int s = blockIdx.y;
    const int row = blockIdx.x;
    const int idx = (s == 0) ? *a.ia : *a.ib;
    const float* __restrict__ xr = a.lg[idx] + (size_t)row * KN;
    const int tid = threadIdx.x, wid = tid >> 5, lane = tid & 31;

    // infra zeroing (once per launch)
    if (blockIdx.x == 0 && s == 0) {
        if (tid < 4) g_flagw[tid] = 0u;
        if (tid == 0) { g_count = 0u; g_release = 0u; }
    }

    // single global pass: stage + row max
    float m = -3.402823466e38f;
    for (int k = tid; k < KN; k += 256) {
        float x = xr[k];
        s_x[k] = x;
        m = fmaxf(m, x);
    }
    m = warp_max(m);
    if (lane == 0) smx[wid] = m;
    __syncthreads();
    if (wid == 0) {
        float t = (lane < 8) ? smx[lane] : -3.402823466e38f;
        t = warp_max(t);
        if (lane == 0) smx[0] = t;
    }
    if (tid == 0) s_base = 0;
    __syncthreads();
    m = smx[0];

    // deterministic k-ordered compaction from smem (R7-exact)
    float rsum = 0.f;
    for (int k0 = 0; k0 < KN; k0 += 256) {
        const int col = k0 + tid;
        bool pred = false;
        float val = 0.f;
        if (col < KN) {
            float d = 20.0f * (s_x[col] - m);
            if (d > THRESH) { pred = true; val = __expf(d); }
        }
        unsigned mask = __ballot_sync(0xffffffffu, pred);
        int wcnt = __popc(mask);
        if (lane == 0) s_wc[wid] = wcnt;
        __syncthreads();
        if (tid == 0) {
            int b = s_base;
#pragma unroll
            for (int w = 0; w < 8; w++) { s_woff[w] = b; b += s_wc[w]; }
            s_base = b;
        }
        __syncthreads();
        if (pred) {
            int pos = s_woff[wid] + __popc(mask & ((1u << lane) - 1u));
            if (pos < CAP) {
                g_nzi[s][row][pos] = (unsigned short)col;
                g_nzv[s][row][pos] = val;
                rsum += val;
            }
        }
        __syncthreads();
    }
    if (tid == 0) g_cnt[s][row] = min(s_base, CAP);

    rsum = warp_sum(rsum);
    if (lane == 0) smx[wid] = rsum;
    __syncthreads();
    if (wid == 0) {
        float t = (lane < 8) ? smx[lane] : 0.f;
        t = warp_sum(t);
        if (lane == 0) g_r[s][row] = t;
    }
}

// ---------------- kernel 1b: block-flattened lists (R7-exact) ----------------
__global__ void __launch_bounds__(256) blockify_kernel() {
    const int s = blockIdx.y, bi = blockIdx.x;
    const int tid = threadIdx.x;
    const int row0 = bi * RPB;
    const int nrow = max(0, min(BN, row0 + RPB) - row0);
    __shared__ int s_off[RPB + 1];
    if (tid == 0) {
        int o = 0;
        for (int b = 0; b < nrow; b++) { s_off[b] = o; o += g_cnt[s][row0 + b]; }
        s_off[nrow] = o;
        g_bcnt[s][bi] = o;
    }
    __syncthreads();
    for (int j = tid; j < nrow * CAP; j += 256) {
        int b = j >> 10, i = j & (CAP - 1);
        if (i < g_cnt[s][row0 + b]) {
            int dst = s_off[b] + i;
            g_bk[s][bi][dst] = (unsigned)g_nzi[s][row0 + b][i] | ((unsigned)b << 16);
            g_bv[s][bi][dst] = g_nzv[s][row0 + b][i];
        }
    }
}

// ---------------- kernel 2: persistent sparse double-Sinkhorn (R7 values, fast sync) ----------------
#define DSMEM_SZ (49152 + 24576 + 1024 + 1024)

__global__ void __launch_bounds__(NTHR, 1) sinkhorn_kernel() {
    extern __shared__ ull dsm[];
    ull* s_c = dsm;                                        // [2][3072] fixed-point scatter
    float* s_v = (float*)(dsm + 2 * KPADC);                // [2][3072]
    float* s_tmp = (float*)(s_v + 2 * KPADC);              // [8*COLSP] cross-warp reduce
    float* s_r = s_tmp + 8 * COLSP + 8;                    // [2][28]
    float* s_u = s_r + 2 * RPB;                            // [2][28]
    float* s_red = s_u + 2 * RPB;                          // [32]
    int* s_cnt = (int*)(s_red + 32);                       // [2][28]

    const int tid = threadIdx.x, bi = blockIdx.x;
    const int wid = tid >> 5, lane = tid & 31;
    const int nwarp = NTHR / 32;
    const float TGT = (float)(4096.0 / 3000.0);
    const int row0 = bi * RPB;
    const int nrow = max(0, min(BN, row0 + RPB) - row0);
    const int k0 = bi * COLSP;
    unsigned gen = 0;

    for (int j = tid; j < 2 * KPADC; j += NTHR) s_c[j] = 0ull;
    for (int s = 0; s < 2; s++)
        if (tid < nrow) {
            s_r[s * RPB + tid] = g_r[s][row0 + tid];
            s_cnt[s * RPB + tid] = g_cnt[s][row0 + tid];
        }
    __syncthreads();

    bool done0 = false, done1 = false;
    int it = 0;

// central-release grid barrier (all NBLK blocks co-resident); value-neutral vs R7
#define GRIDBAR() do { \
        __syncthreads(); \
        gen++; \
        if (tid == 0) { \
            __threadfence(); \
            if (atomicAdd(&g_count, 1u) == NBLK - 1) { \
                g_count = 0u; \
                __threadfence(); \
                g_release = gen; \
            } else { \
                while (g_release < gen) { } \
            } \
            __threadfence(); \
        } \
        __syncthreads(); \
    } while (0)

    while (!(done0 && done1)) {
        const int p = it & 1;
        // --- phase A: u = 1/(r+TINY); fixed-point smem scatter; export fp32 partials ---
        for (int s = 0; s < 2; s++) {
            if (s == 0 ? done0 : done1) continue;
            if (tid < nrow)
                s_u[s * RPB + tid] = 1.0f / (s_r[s * RPB + tid] + 1e-12f);
        }
        __syncthreads();
        for (int s = 0; s < 2; s++) {
            if (s == 0 ? done0 : done1) continue;
            const int bc = g_bcnt[s][bi];
            for (int j = tid; j < bc; j += NTHR) {
                unsigned pk = g_bk[s][bi][j];
                float val = g_bv[s][bi][j];
                float t = s_u[s * RPB + (pk >> 16)] * val;
                atomicAdd(&s_c[s * KPADC + (pk & 0xFFFFu)], __float2ull_rn(t * FXSCALE));
            }
        }
        __syncthreads();
        for (int s = 0; s < 2; s++) {
            if (s == 0 ? done0 : done1) continue;
            for (int j = tid; j < KPADC; j += NTHR) {
                g_cpart[s][bi][j] = (float)s_c[s * KPADC + j] * FXINV;
                s_c[s * KPADC + j] = 0ull;
            }
        }
        GRIDBAR();
        // --- phase B: coalesced owner-column reduce -> c (exact R7 8-warp strided order) ---
        if (bi == 0 && tid < 2) g_flagw[(p ^ 1) * 2 + tid] = 0u;
        for (int s = 0; s < 2; s++) {
            if (s == 0 ? done0 : done1) continue;
            float facc = 0.f;
            if (wid < 8 && lane < COLSP && k0 + lane < KN)
                for (int i = wid; i < NBLK; i += 8) facc += g_cpart[s][i][k0 + lane];
            if (wid < 8 && lane < COLSP) s_tmp[wid * COLSP + lane] = facc;
            __syncthreads();
            if (wid == 0 && lane < COLSP && k0 + lane < KN) {
                float t = 0.f;
#pragma unroll
                for (int w = 0; w < 8; w++) t += s_tmp[w * COLSP + lane];
                g_c[s][k0 + lane] = t;
            }
            __syncthreads();
        }
        GRIDBAR();
        // --- phase C: stage v, col err, gather r, row err (R7-exact values) ---
        {
            float ce0 = 0.f, ce1 = 0.f;
            for (int j = tid; j < 2 * KPADC; j += NTHR) {
                const int s = j / KPADC, k = j % KPADC;
                float v = 0.f;
                if (k < KN && !(s == 0 ? done0 : done1)) {
                    float c = g_c[s][k];
                    v = TGT / (c + 1e-12f);
                    float e = fabsf(v * c - TGT);
                    if (s == 0) ce0 = fmaxf(ce0, e); else ce1 = fmaxf(ce1, e);
                }
                s_v[j] = v;
            }
            ce0 = warp_max(ce0);
            ce1 = warp_max(ce1);
            if (lane == 0) { s_red[wid] = ce0; s_red[16 + wid] = ce1; }
            __syncthreads();
            if (tid == 0) {
                float t0 = 0.f, t1 = 0.f;
                for (int w = 0; w < nwarp; w++) { t0 = fmaxf(t0, s_red[w]); t1 = fmaxf(t1, s_red[16 + w]); }
                if (t0 > TOLF) g_flagw[p * 2 + 0] = 1u;
                if (t1 > TOLF) g_flagw[p * 2 + 1] = 1u;
            }
            __syncthreads();
        }
        for (int job = wid; job < 2 * RPB; job += nwarp) {
            const int s = job / RPB, b = job % RPB;
            if ((s == 0 ? done0 : done1) || b >= nrow) continue;
            const int cnt = s_cnt[s * RPB + b];
            const unsigned short* __restrict__ ri = g_nzi[s][row0 + b];
            const float* __restrict__ rv = g_nzv[s][row0 + b];
            float acc = 0.f;
            for (int i = lane; i < cnt; i += 32)
                acc = fmaf(rv[i], s_v[s * KPADC + ri[i]], acc);
            acc = warp_sum(acc);
            if (lane == 0) {
                s_r[s * RPB + b] = acc;
                if (fabsf(s_u[s * RPB + b] * acc - 1.0f) > TOLF) g_flagw[p * 2 + s] = 1u;
            }
        }
        GRIDBAR();
        it++;
        if (!done0) done0 = (it >= 3) && ((it >= 100) || (g_flagw[p * 2 + 0] == 0u));
        if (!done1) done1 = (it >= 3) && ((it >= 100) || (g_flagw[p * 2 + 1] == 0u));
    }

    // ---------------- finalize (R7-exact) ----------------
    // F1: u1 = u/clip(u*r); scatter with u1
    for (int s = 0; s < 2; s++)
        if (tid < nrow) {
            float u = s_u[s * RPB + tid], r = s_r[s * RPB + tid];
            s_u[s * RPB + tid] = u / fmaxf(u * r, 1e-12f);
        }
    __syncthreads();
    for (int s = 0; s < 2; s++) {
        const int bc = g_bcnt[s][bi];
        for (int j = tid; j < bc; j += NTHR) {
            unsigned pk = g_bk[s][bi][j];
            float val = g_bv[s][bi][j];
            float t = s_u[s * RPB + (pk >> 16)] * val;
            atomicAdd(&s_c[s * KPADC + (pk & 0xFFFFu)], __float2ull_rn(t * FXSCALE));
        }
    }
    __syncthreads();
    for (int j = tid; j < 2 * KPADC; j += NTHR)
        g_cpart[j / KPADC][bi][j % KPADC] = (float)s_c[j] * FXINV;
    GRIDBAR();
    // F2: v2 = v*TGT/clip(v*c2), coalesced owner reduce (8-warp strided order)
    for (int s = 0; s < 2; s++) {
        float facc = 0.f;
        if (wid < 8 && lane < COLSP && k0 + lane < KN)
            for (int i = wid; i < NBLK; i += 8) facc += g_cpart[s][i][k0 + lane];
        if (wid < 8 && lane < COLSP) s_tmp[wid * COLSP + lane] = facc;
        __syncthreads();
        if (wid == 0 && lane < COLSP && k0 + lane < KN) {
            float c2 = 0.f;
#pragma unroll
            for (int w = 0; w < 8; w++) c2 += s_tmp[w * COLSP + lane];
            float v = TGT / (g_c[s][k0 + lane] + 1e-12f);
            g_v2[s][k0 + lane] = v * TGT / fmaxf(v * c2, 1e-12f);
        }
        __syncthreads();
    }
    GRIDBAR();
    // F3: r2 = Q v2; u2; entropy + rowmax; store w
    for (int j = tid; j < 2 * KPADC; j += NTHR) {
        const int s = j / KPADC, k = j % KPADC;
        s_v[j] = (k < KN) ? g_v2[s][k] : 0.f;
    }
    __syncthreads();
    for (int job = wid; job < 2 * RPB; job += nwarp) {
        const int s = job / RPB, b = job % RPB;
        if (b >= nrow) continue;
        const int cnt = s_cnt[s * RPB + b];
        const unsigned short* __restrict__ ri = g_nzi[s][row0 + b];
        const float* __restrict__ rv = g_nzv[s][row0 + b];
        float acc = 0.f;
        for (int i = lane; i < cnt; i += 32)
            acc = fmaf(rv[i], s_v[s * KPADC + ri[i]], acc);
        acc = warp_sum(acc);
        float u1 = s_u[s * RPB + b];
        float u2 = u1 / fmaxf(u1 * acc, 1e-12f);
        float se = 0.f, mq = 0.f;
        for (int i = lane; i < cnt; i += 32) {
            float w = u2 * rv[i] * s_v[s * KPADC + ri[i]];
            g_nzw[s][row0 + b][i] = w;
            se = fmaf(w, __logf(w + 1e-12f), se);
            mq = fmaxf(mq, w);
        }
        se = warp_sum(se);
        mq = warp_max(mq);
        if (lane == 0) {
            g_rowent[s][row0 + b] = se;
            g_rowmaxq[s][row0 + b] = mq;
        }
    }
}

// ---------------- kernel 3: loss, one row per block ----------------
__global__ void __launch_bounds__(256) loss_kernel(Args a) {
    __shared__ __align__(16) float s_x[KN];
    __shared__ float s_red[8];
    __shared__ float s_ab[2];
    const int tid = threadIdx.x, wid = tid >> 5, lane = tid & 31;
    const int c = blockIdx.y, b = blockIdx.x;
    const float* __restrict__ xr = a.lg[c] + (size_t)b * KN;

    // stage row (float4) + max
    float m = -3.402823466e38f;
    {
        const float4* __restrict__ x4 = (const float4*)xr;
        float4* s4 = (float4*)s_x;
        for (int i = tid; i < KN / 4; i += 256) {
            float4 v = __ldg(x4 + i);
            s4[i] = v;
            m = fmaxf(fmaxf(m, fmaxf(v.x, v.y)), fmaxf(v.z, v.w));
        }
    }
    m = warp_max(m);
    if (lane == 0) s_red[wid] = m;
    __syncthreads();
    if (wid == 0) {
        float t = (lane < 8) ? s_red[lane] : -3.402823466e38f;
        t = warp_max(t);
        if (lane == 0) s_red[0] = t;
    }
    __syncthreads();
    m = s_red[0];
    __syncthreads();

    float se = 0.f;
    for (int k = tid; k < KN; k += 256) {
        float d = 10.0f * (s_x[k] - m);
        if (d > -18.f) se += __expf(d);
    }
    se = warp_sum(se);
    if (lane == 0) s_red[wid] = se;

    if (wid < 2) {
        const int s = wid;
        const int cnt = g_cnt[s][b];
        const unsigned short* __restrict__ ri = g_nzi[s][b];
        const float* __restrict__ wv = g_nzw[s][b];
        float dd = 0.f;
        for (int i = lane; i < cnt; i += 32)
            dd = fmaf(wv[i], s_x[(int)ri[i]], dd);
        dd = warp_sum(dd);
        if (lane == 0) s_ab[s] = dd;
    }
    __syncthreads();
    if (tid == 0) {
        float ts = 0.f;
        for (int w = 0; w < 8; w++) ts += s_red[w];
        float* p = &g_losspart[((size_t)c * BN + b) * 3];
        p[0] = 10.0f * m + logf(ts);
        p[1] = s_ab[0];
        p[2] = s_ab[1];
    }
}

// ---------------- kernel 4: final scalar reduction ----------------
__device__ double bredD(double v, double* sd) {
    const int tid = threadIdx.x, wid = tid >> 5, lane = tid & 31;
#pragma unroll
    for (int o = 16; o; o >>= 1) v += __shfl_xor_sync(0xffffffffu, v, o);
    if (lane == 0) sd[wid] = v;
    __syncthreads();
    double t = 0.0;
    if (wid == 0) {
        t = sd[lane];
#pragma unroll
        for (int o = 16; o; o >>= 1) t += __shfl_xor_sync(0xffffffffu, t, o);
    }
    __syncthreads();
    return t;
}

__global__ void __launch_bounds__(1024) fin_kernel(Args a, float* out) {
    __shared__ double sd[32];
    const int tid = threadIdx.x;
    const int ia = *a.ia, ib = *a.ib;
    double se0 = 0, se1 = 0, sm0 = 0, sm1 = 0, sl = 0;
    for (int b = tid; b < BN; b += 1024) {
        se0 += (double)g_rowent[0][b];
        se1 += (double)g_rowent[1][b];
        sm0 += (double)g_rowmaxq[0][b];
        sm1 += (double)g_rowmaxq[1][b];
    }
    for (int i = tid; i < CN * BN; i += 1024) {
        int c = i / BN;
        const float* p = &g_losspart[(size_t)i * 3];
        double lse = p[0];
        if (c != ia) sl += lse - 10.0 * (double)p[1];
        if (c != ib) sl += lse - 10.0 * (double)p[2];
    }
    se0 = bredD(se0, sd);
    se1 = bredD(se1, sd);
    sm0 = bredD(sm0, sd);
    sm1 = bredD(sm1, sd);
    sl = bredD(sl, sd);
    if (tid == 0) {
        out[0] = (float)(sl / (14.0 * BN));
        out[1] = (float)(0.5 * ((-se0 / BN) + (-se1 / BN)));
        out[2] = (float)(0.5 * ((sm0 + sm1) / BN));
    }
}

// ---------------- entry ----------------
extern "C" void kernel_launch(void* const* d_in, const int* in_sizes, int n_in,
                              void* d_out, int out_size) {
    Args a;
    for (int i = 0; i < 8; i++) a.lg[i] = (const float*)d_in[i];
    a.ia = (const int*)d_in[8];
    a.ib = (const int*)d_in[9];

    cudaFuncSetAttribute(sinkhorn_kernel,
                         cudaFuncAttributeMaxDynamicSharedMemorySize, DSMEM_SZ);

    buildq_kernel<<<dim3(BN, 2), 256>>>(a);
    blockify_kernel<<<dim3(NBLK, 2), 256>>>();
    sinkhorn_kernel<<<NBLK, NTHR, DSMEM_SZ>>>();
    loss_kernel<<<dim3(BN, CN), 256>>>(a);
    fin_kernel<<<1, 1024>>>(a, (float*)d_out);
}

// round 13
// speedup vs baseline: 2.0163x; 1.2492x over previous
#include <cuda_runtime.h>
#include <math.h>

#define BN 4096
#define KN 3000
#define KPADC 3072        // padded columns
#define CN 8
#define NBLK 148
#define NTHR 1024
#define RPB 28            // ceil(4096/148)
#define CAP 1024          // max nz per row (power of 2)
#define BCAP (RPB*CAP)    // max nz per block
#define COLSP 21          // ceil(3000/148)
#define TOLF 1e-3f
#define THRESH -36.0f
#define FXSCALE 4398046511104.0f       // 2^42
#define FXINV   (1.0f/4398046511104.0f)

typedef unsigned long long ull;

// ---------------- static scratch ----------------
static __device__ unsigned short g_nzi[2][BN][CAP];   // column index per nz
static __device__ float g_nzv[2][BN][CAP];            // exp value per nz
static __device__ float g_nzw[2][BN][CAP];            // final P value per nz
static __device__ int   g_cnt[2][BN];
static __device__ unsigned g_bk[2][NBLK][BCAP];       // packed k | (localrow<<16)
static __device__ float g_bv[2][NBLK][BCAP];
static __device__ int   g_bcnt[2][NBLK];
static __device__ float g_cpart[2][NBLK][KPADC];      // fp32 column partials
static __device__ float g_c[2][KPADC];                // reduced column sums
static __device__ float g_v2[2][KPADC];               // final v
static __device__ float g_r[2][BN];                   // row sums (initial)
static __device__ volatile unsigned g_arrive[NBLK];   // barrier arrival flags
static __device__ volatile unsigned g_release;        // barrier release word
static __device__ volatile unsigned g_flagw[4];       // [slot][side]
static __device__ float g_rowent[2][BN];
static __device__ float g_rowmaxq[2][BN];
static __device__ float g_losspart[(size_t)CN * BN * 3];

struct Args {
    const float* lg[8];
    const int* ia;
    const int* ib;
};

__device__ __forceinline__ float warp_max(float v) {
#pragma unroll
    for (int o = 16; o; o >>= 1) v = fmaxf(v, __shfl_xor_sync(0xffffffffu, v, o));
    return v;
}
__device__ __forceinline__ float warp_sum(float v) {
#pragma unroll
    for (int o = 16; o; o >>= 1) v += __shfl_xor_sync(0xffffffffu, v, o);
    return v;
}

// ---------------- kernel 1: sparse build (single HBM pass) — R7 arithmetic ----------------
__global__ void __launch_bounds__(256) buildq_kernel(Args a) {
    __shared__ float s_x[KN];
    __shared__ float smx[8];
    __shared__ int s_wc[8], s_woff[8], s_base;

    const int s = blockIdx.y;
    const int row = blockIdx.x;
    const int idx = (s == 0) ? *a.ia : *a.ib;
    const float* __restrict__ xr = a.lg[idx] + (size_t)row * KN;
    const int tid = threadIdx.x, wid = tid >> 5, lane = tid & 31;

    // infra zeroing (once per launch — required for graph replay)
    if (blockIdx.x == 0 && s == 0) {
        if (tid < NBLK) g_arrive[tid] = 0u;
        if (tid < 4) g_flagw[tid] = 0u;
        if (tid == 0) g_release = 0u;
    }

    // single global pass: stage + row max
    float m = -3.402823466e38f;
    for (int k = tid; k < KN; k += 256) {
        float x = xr[k];
        s_x[k] = x;
        m = fmaxf(m, x);
    }
    m = warp_max(m);
    if (lane == 0) smx[wid] = m;
    __syncthreads();
    if (wid == 0) {
        float t = (lane < 8) ? smx[lane] : -3.402823466e38f;
        t = warp_max(t);
        if (lane == 0) smx[0] = t;
    }
    if (tid == 0) s_base = 0;
    __syncthreads();
    m = smx[0];

    // deterministic k-ordered compaction from smem (R7-exact)
    float rsum = 0.f;
    for (int k0 = 0; k0 < KN; k0 += 256) {
        const int col = k0 + tid;
        bool pred = false;
        float val = 0.f;
        if (col < KN) {
            float d = 20.0f * (s_x[col] - m);
            if (d > THRESH) { pred = true; val = __expf(d); }
        }
        unsigned mask = __ballot_sync(0xffffffffu, pred);
        int wcnt = __popc(mask);
        if (lane == 0) s_wc[wid] = wcnt;
        __syncthreads();
        if (tid == 0) {
            int b = s_base;
#pragma unroll
            for (int w = 0; w < 8; w++) { s_woff[w] = b; b += s_wc[w]; }
            s_base = b;
        }
        __syncthreads();
        if (pred) {
            int pos = s_woff[wid] + __popc(mask & ((1u << lane) - 1u));
            if (pos < CAP) {
                g_nzi[s][row][pos] = (unsigned short)col;
                g_nzv[s][row][pos] = val;
                rsum += val;
            }
        }
        __syncthreads();
    }
    if (tid == 0) g_cnt[s][row] = min(s_base, CAP);

    rsum = warp_sum(rsum);
    if (lane == 0) smx[wid] = rsum;
    __syncthreads();
    if (wid == 0) {
        float t = (lane < 8) ? smx[lane] : 0.f;
        t = warp_sum(t);
        if (lane == 0) g_r[s][row] = t;
    }
}

// ---------------- kernel 1b: block-flattened lists (R7-exact) ----------------
__global__ void __launch_bounds__(256) blockify_kernel() {
    const int s = blockIdx.y, bi = blockIdx.x;
    const int tid = threadIdx.x;
    const int row0 = bi * RPB;
    const int nrow = max(0, min(BN, row0 + RPB) - row0);
    __shared__ int s_off[RPB + 1];
    if (tid == 0) {
        int o = 0;
        for (int b = 0; b < nrow; b++) { s_off[b] = o; o += g_cnt[s][row0 + b]; }
        s_off[nrow] = o;
        g_bcnt[s][bi] = o;
    }
    __syncthreads();
    for (int j = tid; j < nrow * CAP; j += 256) {
        int b = j >> 10, i = j & (CAP - 1);
        if (i < g_cnt[s][row0 + b]) {
            int dst = s_off[b] + i;
            g_bk[s][bi][dst] = (unsigned)g_nzi[s][row0 + b][i] | ((unsigned)b << 16);
            g_bv[s][bi][dst] = g_nzv[s][row0 + b][i];
        }
    }
}

// ---------------- kernel 2: persistent sparse double-Sinkhorn ----------------
// R7/R12-exact values; 2 barriers/iter (merged C+A), monitor-block barrier, 1024 thr.
#define DSMEM_SZ 76800

__global__ void __launch_bounds__(NTHR, 1) sinkhorn_kernel() {
    extern __shared__ ull dsm[];
    ull* s_c = dsm;                                        // [2][3072] fixed-point scatter
    float* s_v = (float*)(dsm + 2 * KPADC);                // [2][3072]
    float* s_tmp = s_v + 2 * KPADC;                        // [8*COLSP] cross-warp reduce
    float* s_r = s_tmp + 8 * COLSP + 8;                    // [2][28]
    float* s_ucur = s_r + 2 * RPB;                         // [2][28]
    float* s_uprev = s_ucur + 2 * RPB;                     // [2][28]
    float* s_red = s_uprev + 2 * RPB;                      // [64]
    int* s_cnt = (int*)(s_red + 64);                       // [2][28]

    const int tid = threadIdx.x, bi = blockIdx.x;
    const int wid = tid >> 5, lane = tid & 31;
    const int nwarp = NTHR / 32;
    const float TGT = (float)(4096.0 / 3000.0);
    const int row0 = bi * RPB;
    const int nrow = max(0, min(BN, row0 + RPB) - row0);
    const int k0 = bi * COLSP;
    unsigned gen = 0;

// monitor-block grid barrier: plain-store arrivals, block 0 detects, single release word
#define GRIDBAR() do { \
        __syncthreads(); \
        gen++; \
        if (tid == 0) { __threadfence(); g_arrive[bi] = gen; } \
        if (bi == 0) { \
            if (tid < NBLK) { while (g_arrive[tid] < gen) { } } \
            __syncthreads(); \
            if (tid == 0) { __threadfence(); g_release = gen; __threadfence(); } \
            __syncthreads(); \
        } else { \
            if (tid == 0) { while (g_release < gen) { } __threadfence(); } \
            __syncthreads(); \
        } \
    } while (0)

// scatter + export for one side (R7-exact arithmetic; partition value-neutral)
#define SCATTER_EXPORT(s) do { \
        const int bc = g_bcnt[s][bi]; \
        for (int j = tid; j < bc; j += NTHR) { \
            unsigned pk = g_bk[s][bi][j]; \
            float val = g_bv[s][bi][j]; \
            float t = s_ucur[(s) * RPB + (pk >> 16)] * val; \
            atomicAdd(&s_c[(s) * KPADC + (pk & 0xFFFFu)], __float2ull_rn(t * FXSCALE)); \
        } \
    } while (0)

#define EXPORT_CLEAR(s) do { \
        for (int j = tid; j < KPADC; j += NTHR) { \
            g_cpart[s][bi][j] = (float)s_c[(s) * KPADC + j] * FXINV; \
            s_c[(s) * KPADC + j] = 0ull; \
        } \
    } while (0)

// owner-column reduce for one side (exact R7 8-warp stride-8 order)
#define COLREDUCE(s, DST) do { \
        float facc = 0.f; \
        if (wid < 8 && lane < COLSP && k0 + lane < KN) \
            for (int i = wid; i < NBLK; i += 8) facc += g_cpart[s][i][k0 + lane]; \
        if (wid < 8 && lane < COLSP) s_tmp[wid * COLSP + lane] = facc; \
        __syncthreads(); \
        if (wid == 0 && lane < COLSP && k0 + lane < KN) { \
            float t = 0.f; \
            _Pragma("unroll") \
            for (int w = 0; w < 8; w++) t += s_tmp[w * COLSP + lane]; \
            DST; \
        } \
        __syncthreads(); \
    } while (0)

    // init
    for (int j = tid; j < 2 * KPADC; j += NTHR) s_c[j] = 0ull;
    for (int s = 0; s < 2; s++)
        if (tid < nrow) {
            float r = g_r[s][row0 + tid];
            s_r[s * RPB + tid] = r;
            s_cnt[s * RPB + tid] = g_cnt[s][row0 + tid];
            float u1 = 1.0f / (r + 1e-12f);     // u for iteration 1 (R7-exact)
            s_ucur[s * RPB + tid] = u1;
            s_uprev[s * RPB + tid] = u1;
        }
    __syncthreads();

    // prologue: A(1) scatter with u_1, export; B(1) reduce -> c_1
    SCATTER_EXPORT(0);
    SCATTER_EXPORT(1);
    __syncthreads();
    EXPORT_CLEAR(0);
    EXPORT_CLEAR(1);
    GRIDBAR();
    COLREDUCE(0, g_c[0][k0 + lane] = t);
    COLREDUCE(1, g_c[1][k0 + lane] = t);
    GRIDBAR();

    bool done0 = false, done1 = false;
    int it = 1;
    while (true) {
        const int slot = it & 1;
        // ===== CA(it): v_t + colflag + r_t + rowflag + u_{t+1} + scatter + export =====
        {
            float ce0 = 0.f, ce1 = 0.f;
            for (int j = tid; j < 2 * KPADC; j += NTHR) {
                const int s = j / KPADC, k = j % KPADC;
                if (s == 0 ? done0 : done1) continue;   // preserve done side's s_v
                float v = 0.f;
                if (k < KN) {
                    float c = g_c[s][k];
                    v = TGT / (c + 1e-12f);
                    float e = fabsf(v * c - TGT);
                    if (s == 0) ce0 = fmaxf(ce0, e); else ce1 = fmaxf(ce1, e);
                }
                s_v[j] = v;
            }
            ce0 = warp_max(ce0);
            ce1 = warp_max(ce1);
            if (lane == 0) { s_red[wid] = ce0; s_red[32 + wid] = ce1; }
            __syncthreads();
            if (tid == 0) {
                float t0 = 0.f, t1 = 0.f;
                for (int w = 0; w < nwarp; w++) { t0 = fmaxf(t0, s_red[w]); t1 = fmaxf(t1, s_red[32 + w]); }
                if (t0 > TOLF) g_flagw[slot * 2 + 0] = 1u;
                if (t1 > TOLF) g_flagw[slot * 2 + 1] = 1u;
            }
            __syncthreads();
        }
        // row gather r_t (R7-exact per-row order), row flag, u_{t+1}
        for (int job = wid; job < 2 * RPB; job += nwarp) {
            const int s = job / RPB, b = job % RPB;
            if ((s == 0 ? done0 : done1) || b >= nrow) continue;
            const int cnt = s_cnt[s * RPB + b];
            const unsigned short* __restrict__ ri = g_nzi[s][row0 + b];
            const float* __restrict__ rv = g_nzv[s][row0 + b];
            float acc = 0.f;
            for (int i = lane; i < cnt; i += 32)
                acc = fmaf(rv[i], s_v[s * KPADC + ri[i]], acc);
            acc = warp_sum(acc);
            if (lane == 0) {
                float uold = s_ucur[s * RPB + b];
                s_uprev[s * RPB + b] = uold;
                s_r[s * RPB + b] = acc;
                s_ucur[s * RPB + b] = 1.0f / (acc + 1e-12f);
                if (fabsf(uold * acc - 1.0f) > TOLF) g_flagw[slot * 2 + s] = 1u;
            }
        }
        __syncthreads();
        // scatter u_{t+1} for next iteration's c (wasted on final iter — values unused)
        if (!done0) SCATTER_EXPORT(0);
        if (!done1) SCATTER_EXPORT(1);
        __syncthreads();
        if (!done0) EXPORT_CLEAR(0);
        if (!done1) EXPORT_CLEAR(1);
        GRIDBAR();
        // ===== B(it+1): zero next flag slot; reduce -> c_{t+1} =====
        if (bi == 0 && tid < 2) g_flagw[((it + 1) & 1) * 2 + tid] = 0u;
        if (!done0) COLREDUCE(0, g_c[0][k0 + lane] = t);
        if (!done1) COLREDUCE(1, g_c[1][k0 + lane] = t);
        GRIDBAR();
        // ===== decision on iter it (R7-exact semantics) =====
        if (!done0) done0 = (it >= 3) && ((it >= 100) || (g_flagw[slot * 2 + 0] == 0u));
        if (!done1) done1 = (it >= 3) && ((it >= 100) || (g_flagw[slot * 2 + 1] == 0u));
        if (done0 && done1) break;
        it++;
    }

    // ---------------- finalize (R7-exact values) ----------------
    // F1: u1 = u_t/clip(u_t*r_t); scatter with u1
    for (int s = 0; s < 2; s++)
        if (tid < nrow) {
            float u = s_uprev[s * RPB + tid], r = s_r[s * RPB + tid];
            s_ucur[s * RPB + tid] = u / fmaxf(u * r, 1e-12f);
        }
    __syncthreads();
    SCATTER_EXPORT(0);
    SCATTER_EXPORT(1);
    __syncthreads();
    EXPORT_CLEAR(0);
    EXPORT_CLEAR(1);
    GRIDBAR();
    // F2: v2 = v_t*TGT/clip(v_t*c2); v_t from s_v (same value as R12's recompute)
    for (int s = 0; s < 2; s++) {
        COLREDUCE(s, {
            float v = s_v[s * KPADC + k0 + lane];
            g_v2[s][k0 + lane] = v * TGT / fmaxf(v * t, 1e-12f);
        });
    }
    GRIDBAR();
    // F3: r2 = Q v2; u2; entropy + rowmax; store w
    for (int j = tid; j < 2 * KPADC; j += NTHR) {
        const int s = j / KPADC, k = j % KPADC;
        s_v[j] = (k < KN) ? g_v2[s][k] : 0.f;
    }
    __syncthreads();
    for (int job = wid; job < 2 * RPB; job += nwarp) {
        const int s = job / RPB, b = job % RPB;
        if (b >= nrow) continue;
        const int cnt = s_cnt[s * RPB + b];
        const unsigned short* __restrict__ ri = g_nzi[s][row0 + b];
        const float* __restrict__ rv = g_nzv[s][row0 + b];
        float acc = 0.f;
        for (int i = lane; i < cnt; i += 32)
            acc = fmaf(rv[i], s_v[s * KPADC + ri[i]], acc);
        acc = warp_sum(acc);
        float u1 = s_ucur[s * RPB + b];
        float u2 = u1 / fmaxf(u1 * acc, 1e-12f);
        float se = 0.f, mq = 0.f;
        for (int i = lane; i < cnt; i += 32) {
            float w = u2 * rv[i] * s_v[s * KPADC + ri[i]];
            g_nzw[s][row0 + b][i] = w;
            se = fmaf(w, __logf(w + 1e-12f), se);
            mq = fmaxf(mq, w);
        }
        se = warp_sum(se);
        mq = warp_max(mq);
        if (lane == 0) {
            g_rowent[s][row0 + b] = se;
            g_rowmaxq[s][row0 + b] = mq;
        }
    }
}

// ---------------- kernel 3: loss, one row per block, register lse ----------------
__global__ void __launch_bounds__(256) loss_kernel(Args a) {
    __shared__ __align__(16) float s_x[KN];
    __shared__ float s_red[8];
    __shared__ float s_ab[2];
    const int tid = threadIdx.x, wid = tid >> 5, lane = tid & 31;
    const int c = blockIdx.y, b = blockIdx.x;
    const float* __restrict__ xr = a.lg[c] + (size_t)b * KN;

    // stage row to smem + keep in registers; block max
    const float4* __restrict__ x4 = (const float4*)xr;
    float4* s4 = (float4*)s_x;
    float4 ra = __ldg(x4 + tid);
    float4 rb = __ldg(x4 + tid + 256);
    const bool hasc = (tid + 512) < KN / 4;
    float4 rc = hasc ? __ldg(x4 + tid + 512) : make_float4(-1e38f, -1e38f, -1e38f, -1e38f);
    s4[tid] = ra;
    s4[tid + 256] = rb;
    if (hasc) s4[tid + 512] = rc;

    float m = fmaxf(fmaxf(ra.x, ra.y), fmaxf(ra.z, ra.w));
    m = fmaxf(m, fmaxf(fmaxf(rb.x, rb.y), fmaxf(rb.z, rb.w)));
    m = fmaxf(m, fmaxf(fmaxf(rc.x, rc.y), fmaxf(rc.z, rc.w)));
    m = warp_max(m);
    if (lane == 0) s_red[wid] = m;
    __syncthreads();
    if (wid == 0) {
        float t = (lane < 8) ? s_red[lane] : -3.402823466e38f;
        t = warp_max(t);
        if (lane == 0) s_red[0] = t;
    }
    __syncthreads();
    m = s_red[0];
    __syncthreads();

    // lse from registers (no smem reads)
    float se = 0.f;
    {
        float d;
        d = 10.0f * (ra.x - m); if (d > -18.f) se += __expf(d);
        d = 10.0f * (ra.y - m); if (d > -18.f) se += __expf(d);
        d = 10.0f * (ra.z - m); if (d > -18.f) se += __expf(d);
        d = 10.0f * (ra.w - m); if (d > -18.f) se += __expf(d);
        d = 10.0f * (rb.x - m); if (d > -18.f) se += __expf(d);
        d = 10.0f * (rb.y - m); if (d > -18.f) se += __expf(d);
        d = 10.0f * (rb.z - m); if (d > -18.f) se += __expf(d);
        d = 10.0f * (rb.w - m); if (d > -18.f) se += __expf(d);
        if (hasc) {
            d = 10.0f * (rc.x - m); if (d > -18.f) se += __expf(d);
            d = 10.0f * (rc.y - m); if (d > -18.f) se += __expf(d);
            d = 10.0f * (rc.z - m); if (d > -18.f) se += __expf(d);
            d = 10.0f * (rc.w - m); if (d > -18.f) se += __expf(d);
        }
    }
    se = warp_sum(se);
    if (lane == 0) s_red[wid] = se;

    if (wid < 2) {
        const int s = wid;
        const int cnt = g_cnt[s][b];
        const unsigned short* __restrict__ ri = g_nzi[s][b];
        const float* __restrict__ wv = g_nzw[s][b];
        float dd = 0.f;
        for (int i = lane; i < cnt; i += 32)
            dd = fmaf(wv[i], s_x[(int)ri[i]], dd);
        dd = warp_sum(dd);
        if (lane == 0) s_ab[s] = dd;
    }
    __syncthreads();
    if (tid == 0) {
        float ts = 0.f;
        for (int w = 0; w < 8; w++) ts += s_red[w];
        float* p = &g_losspart[((size_t)c * BN + b) * 3];
        p[0] = 10.0f * m + logf(ts);
        p[1] = s_ab[0];
        p[2] = s_ab[1];
    }
}

// ---------------- kernel 4: final scalar reduction ----------------
__device__ double bredD(double v, double* sd) {
    const int tid = threadIdx.x, wid = tid >> 5, lane = tid & 31;
#pragma unroll
    for (int o = 16; o; o >>= 1) v += __shfl_xor_sync(0xffffffffu, v, o);
    if (lane == 0) sd[wid] = v;
    __syncthreads();
    double t = 0.0;
    if (wid == 0) {
        t = sd[lane];
#pragma unroll
        for (int o = 16; o; o >>= 1) t += __shfl_xor_sync(0xffffffffu, t, o);
    }
    __syncthreads();
    return t;
}

__global__ void __launch_bounds__(1024) fin_kernel(Args a, float* out) {
    __shared__ double sd[32];
    const int tid = threadIdx.x;
    const int ia = *a.ia, ib = *a.ib;
    double se0 = 0, se1 = 0, sm0 = 0, sm1 = 0, sl = 0;
    for (int b = tid; b < BN; b += 1024) {
        se0 += (double)g_rowent[0][b];
        se1 += (double)g_rowent[1][b];
        sm0 += (double)g_rowmaxq[0][b];
        sm1 += (double)g_rowmaxq[1][b];
    }
    for (int i = tid; i < CN * BN; i += 1024) {
        int c = i / BN;
        const float* p = &g_losspart[(size_t)i * 3];
        double lse = p[0];
        if (c != ia) sl += lse - 10.0 * (double)p[1];
        if (c != ib) sl += lse - 10.0 * (double)p[2];
    }
    se0 = bredD(se0, sd);
    se1 = bredD(se1, sd);
    sm0 = bredD(sm0, sd);
    sm1 = bredD(sm1, sd);
    sl = bredD(sl, sd);
    if (tid == 0) {
        out[0] = (float)(sl / (14.0 * BN));
        out[1] = (float)(0.5 * ((-se0 / BN) + (-se1 / BN)));
        out[2] = (float)(0.5 * ((sm0 + sm1) / BN));
    }
}

// ---------------- entry ----------------
extern "C" void kernel_launch(void* const* d_in, const int* in_sizes, int n_in,
                              void* d_out, int out_size) {
    Args a;
    for (int i = 0; i < 8; i++) a.lg[i] = (const float*)d_in[i];
    a.ia = (const int*)d_in[8];
    a.ib = (const int*)d_in[9];

    cudaFuncSetAttribute(sinkhorn_kernel,
                         cudaFuncAttributeMaxDynamicSharedMemorySize, DSMEM_SZ);

    buildq_kernel<<<dim3(BN, 2), 256>>>(a);
    blockify_kernel<<<dim3(NBLK, 2), 256>>>();
    sinkhorn_kernel<<<NBLK, NTHR, DSMEM_SZ>>>();
    loss_kernel<<<dim3(BN, CN), 256>>>(a);
    fin_kernel<<<1, 1024>>>(a, (float*)d_out);
}